// round 13
// baseline (speedup 1.0000x reference)
#include <cuda_runtime.h>
#include <math.h>
#include <stdint.h>

#define BB 32
#define TT 512
#define DD 512
#define LL 2048
// C2 = SIGMA * log2(e) = 0.2 * 1.4426950408889634
#define C2 0.28853901f

#define WLIM 80.0f      // window threshold: dropped terms <= 1.1e-7 rel
#define RAD  26.0f      // attn row radius (covers all band-nonzero interior)
#define TAILG 50.0f     // tail token slack
#define BW   16         // band width (tokens per l)
#define WU   32         // union window cap in aligned
#define LT2  16         // l's per aligned block

__device__ float  g_starts[BB * TT];
__device__ int    g_tlocnt[BB * LL];         // tlo | (cnt<<16)
__device__ float4 g_band4 [BB * LL * 4];     // [bl][j/4], l-major, normalized

// ---------------------------------------------------------------------------
// Fast 2^x for x in [-126, 0]; ~2e-6 relative accuracy, FMA pipe only.
// ---------------------------------------------------------------------------
__device__ __forceinline__ float exp2_fast(float x) {
    float t = __fadd_rn(x, 12582912.0f);
    int   e = __float_as_int(t) - 0x4B400000;
    float f = __fsub_rn(x, __fsub_rn(t, 12582912.0f));
    float p =             1.3333558e-3f;
    p = fmaf(p, f, 9.6181291e-3f);
    p = fmaf(p, f, 5.5504109e-2f);
    p = fmaf(p, f, 2.4022651e-1f);
    p = fmaf(p, f, 6.9314718e-1f);
    p = fmaf(p, f, 1.0f);
    return p * __int_as_float((e + 127) << 23);
}

__device__ __forceinline__ float gw(float lf, float st, float dmin2) {
    float d = lf - st;
    float arg = fmaxf((dmin2 - d * d) * C2, -125.0f);
    return exp2_fast(arg);
}

// ---------------------------------------------------------------------------
// K0: scan.  One block per batch; fp64 shuffle scan -> g_starts.
// ---------------------------------------------------------------------------
__global__ void __launch_bounds__(512)
scan_kernel(const float* __restrict__ dur) {
    __shared__ double wsum[16];
    int b   = blockIdx.x;
    int tid = threadIdx.x;
    int lane = tid & 31, warp = tid >> 5;

    float v = dur[b * TT + tid];
    double d = (double)v;
    #pragma unroll
    for (int off = 1; off < 32; off <<= 1) {
        double n = __shfl_up_sync(0xffffffffu, d, off);
        if (lane >= off) d += n;
    }
    if (lane == 31) wsum[warp] = d;
    __syncthreads();
    if (tid < 16) {
        double w = wsum[tid];
        #pragma unroll
        for (int off = 1; off < 16; off <<= 1) {
            double n = __shfl_up_sync(0xffffu, w, off);
            if (tid >= off) w += n;
        }
        wsum[tid] = w;
    }
    __syncthreads();
    double base = warp ? wsum[warp - 1] : 0.0;
    g_starts[b * TT + tid] = (float)(base + d - (double)v);  // exclusive
}

// ---------------------------------------------------------------------------
// K1: band.  Grid (16, 32) x 128 threads: block loads its batch's starts
// into smem (coalesced), then 1 thread per l runs the proven R10 chain.
// ---------------------------------------------------------------------------
__global__ void __launch_bounds__(128)
band_kernel() {
    __shared__ float s[TT];
    int b   = blockIdx.y;
    int tid = threadIdx.x;

    #pragma unroll
    for (int i = 0; i < 4; i++)
        s[tid + 128 * i] = g_starts[b * TT + tid + 128 * i];
    __syncthreads();

    int l = blockIdx.x * 128 + tid;
    float lf = (float)l;

    // nearest token: last t with s[t] <= lf
    int last = 0;
    #pragma unroll
    for (int step = 256; step > 0; step >>= 1) {
        int c = last + step;
        if (c < TT && s[c] <= lf) last = c;
    }
    int tn = last;
    float d0 = lf - s[last];
    float dmin2 = d0 * d0;
    if (last + 1 < TT) {
        float d1 = s[last + 1] - lf;
        if (d1 * d1 < dmin2) { tn = last + 1; dmin2 = d1 * d1; }
    }
    float limit = dmin2 + WLIM;
    float r  = sqrtf(limit);
    float lb = lf - r;
    float ub = lf + r;

    // two independent 9-step searches
    int p1 = 0, p2 = 0;
    #pragma unroll
    for (int step = 256; step > 0; step >>= 1) {
        int c1 = p1 + step, c2 = p2 + step;
        if (c1 < TT && s[c1] <  lb) p1 = c1;
        if (c2 < TT && s[c2] <= ub) p2 = c2;
    }
    int lo = (s[0] < lb) ? p1 + 1 : 0;
    int hi = p2;
    lo = max(lo, tn - 12);  lo = min(lo, tn);
    hi = min(hi, tn + 12);  hi = max(hi, tn);
    if (hi - lo + 1 > BW) {
        #pragma unroll
        for (int i = 0; i < 9; i++) {
            if (hi - lo + 1 > BW) {
                float dl = lf - s[lo], dh = s[hi] - lf;
                if (dl >= dh) lo++; else hi--;
            }
        }
    }
    int cnt = min(hi - lo + 1, BW);

    float ws[BW];
    float sum = 0.0f;
    #pragma unroll
    for (int j = 0; j < BW; j++) {
        int t = min(lo + j, TT - 1);
        float w = (j < cnt) ? gw(lf, s[t], dmin2) : 0.0f;
        ws[j] = w;
        sum += w;
    }
    float inv = 1.0f / sum;
    int bl = b * LL + l;
    float4* bp = g_band4 + (size_t)bl * 4;
    #pragma unroll
    for (int q = 0; q < 4; q++)
        bp[q] = make_float4(ws[4*q] * inv, ws[4*q+1] * inv,
                            ws[4*q+2] * inv, ws[4*q+3] * inv);
    g_tlocnt[bl] = lo | (cnt << 16);
}

// ---------------------------------------------------------------------------
// K2: aligned (proven R10 shape: 4-l groups x half-D warps, unroll 2,
// coalesced float4 band fill + smem scatter).
// ---------------------------------------------------------------------------
__device__ __forceinline__ void fma4(float4& a, float w, float4 v) {
    a.x = fmaf(w, v.x, a.x); a.y = fmaf(w, v.y, a.y);
    a.z = fmaf(w, v.z, a.z); a.w = fmaf(w, v.w, a.w);
}

__global__ void __launch_bounds__(256, 4)
aligned_kernel(const float* __restrict__ x, float* __restrict__ out) {
    __shared__ float wb[LT2][WU];
    __shared__ int   tlo_s[LT2], thi_s[LT2];
    __shared__ int   ulo_s[4], ucnt_s[4];

    int b   = blockIdx.y;
    int l0  = blockIdx.x * LT2;
    int tid = threadIdx.x;

    // zero wb (512 floats)
    ((float*)wb)[tid] = 0.0f;
    ((float*)wb)[tid + 256] = 0.0f;

    if (tid < LT2) {
        int tc = g_tlocnt[b * LL + l0 + tid];
        int lo = tc & 0xffff;
        tlo_s[tid] = lo;
        thi_s[tid] = lo + (tc >> 16);        // exclusive hi
    }
    __syncthreads();
    if (tid < 4) {
        int ulo = tlo_s[4 * tid], uhi = thi_s[4 * tid];
        #pragma unroll
        for (int i = 1; i < 4; i++) {
            ulo = min(ulo, tlo_s[4 * tid + i]);
            uhi = max(uhi, thi_s[4 * tid + i]);
        }
        ulo_s[tid]  = ulo;
        ucnt_s[tid] = min(uhi - ulo, WU);
    }
    __syncthreads();
    // coalesced band fetch: 64 threads load 64 float4s (16 l x 4)
    if (tid < LT2 * 4) {
        int li = tid >> 2, q = tid & 3;
        float4 bv = g_band4[(size_t)(b * LL + l0 + li) * 4 + q];
        int sh = tlo_s[li] - ulo_s[li >> 2];    // >= 0
        int k0 = sh + 4 * q;
        if (k0 + 0 < WU) wb[li][k0 + 0] = bv.x;
        if (k0 + 1 < WU) wb[li][k0 + 1] = bv.y;
        if (k0 + 2 < WU) wb[li][k0 + 2] = bv.z;
        if (k0 + 3 < WU) wb[li][k0 + 3] = bv.w;
    }
    __syncthreads();

    int warp = tid >> 5, lane = tid & 31;
    int g = warp >> 1;          // l-group (0..3)
    int h = warp & 1;           // D half
    int ulo  = ulo_s[g];
    int ucnt = ucnt_s[g];
    int wrow = g * 4;

    float4 a00 = make_float4(0.f,0.f,0.f,0.f), a01 = a00;
    float4 a10 = a00, a11 = a00;
    float4 a20 = a00, a21 = a00;
    float4 a30 = a00, a31 = a00;

    const float4* xb =
        (const float4*)(x + ((size_t)b * TT + ulo) * DD) + h * 64 + lane;
    #pragma unroll 2
    for (int k = 0; k < ucnt; k++) {
        const float4* xr = xb + (size_t)k * (DD / 4);
        float4 v0 = xr[0], v1 = xr[32];
        float w0 = wb[wrow + 0][k];
        float w1 = wb[wrow + 1][k];
        float w2 = wb[wrow + 2][k];
        float w3 = wb[wrow + 3][k];
        fma4(a00, w0, v0); fma4(a01, w0, v1);
        fma4(a10, w1, v0); fma4(a11, w1, v1);
        fma4(a20, w2, v0); fma4(a21, w2, v1);
        fma4(a30, w3, v0); fma4(a31, w3, v1);
    }

    {
        float4* op = (float4*)(out + ((size_t)b * LL + (l0 + wrow + 0)) * DD)
                     + h * 64 + lane;
        __stcs(op, a00); __stcs(op + 32, a01);
    }
    {
        float4* op = (float4*)(out + ((size_t)b * LL + (l0 + wrow + 1)) * DD)
                     + h * 64 + lane;
        __stcs(op, a10); __stcs(op + 32, a11);
    }
    {
        float4* op = (float4*)(out + ((size_t)b * LL + (l0 + wrow + 2)) * DD)
                     + h * 64 + lane;
        __stcs(op, a20); __stcs(op + 32, a21);
    }
    {
        float4* op = (float4*)(out + ((size_t)b * LL + (l0 + wrow + 3)) * DD)
                     + h * 64 + lane;
        __stcs(op, a30); __stcs(op + 32, a31);
    }
}

// ---------------------------------------------------------------------------
// K3: attn rows from band.  One warp per (b,t) row; streaming stores.
// ---------------------------------------------------------------------------
__global__ void attn_rows_kernel(float* __restrict__ attn) {
    int warp = threadIdx.x >> 5, lane = threadIdx.x & 31;
    int row  = blockIdx.x * 8 + warp;
    int b = row / TT, t = row % TT;

    float st    = g_starts[b * TT + t];
    float slast = g_starts[b * TT + TT - 1];
    bool  tail  = (st >= slast - TAILG);
    int lmin = max(0, (int)floorf(st - RAD));
    int lmax = tail ? (LL - 1) : min(LL - 1, (int)ceilf(st + RAD));

    const int*   tlc = g_tlocnt + b * LL;
    const float* bnd = (const float*)g_band4;
    float4* rowp = (float4*)(attn + ((size_t)b * TT + t) * LL);

    #pragma unroll
    for (int k = 0; k < 16; k++) {
        int l0 = 128 * k + 4 * lane;
        float4 vq = make_float4(0.f, 0.f, 0.f, 0.f);
        if (l0 + 3 >= lmin && l0 <= lmax) {
            float* vp = &vq.x;
            #pragma unroll
            for (int j = 0; j < 4; j++) {
                int l = l0 + j;
                if (l >= lmin && l <= lmax) {
                    int off = t - (tlc[l] & 0xffff);
                    if (off >= 0 && off < BW)
                        vp[j] = bnd[(size_t)(b * LL + l) * BW + off];
                }
            }
        }
        __stcs(rowp + (l0 >> 2), vq);
    }
}

// ---------------------------------------------------------------------------
extern "C" void kernel_launch(void* const* d_in, const int* in_sizes, int n_in,
                              void* d_out, int out_size) {
    const float* x   = (const float*)d_in[0];
    const float* dur = (const float*)d_in[1];
    float* out     = (float*)d_out;
    float* aligned = out;                          // (B, L, D)
    float* attn    = out + (size_t)BB * LL * DD;   // (B, T, L)

    scan_kernel<<<BB, 512>>>(dur);
    band_kernel<<<dim3(LL / 128, BB), 128>>>();
    aligned_kernel<<<dim3(LL / LT2, BB), 256>>>(x, aligned);
    attn_rows_kernel<<<(BB * TT) / 8, 256>>>(attn);
}

// round 14
// speedup vs baseline: 1.0524x; 1.0524x over previous
#include <cuda_runtime.h>
#include <math.h>
#include <stdint.h>

#define BB 32
#define TT 512
#define DD 512
#define LL 2048
// C2 = SIGMA * log2(e) = 0.2 * 1.4426950408889634
#define C2 0.28853901f

#define WLIM 80.0f      // window threshold: dropped terms <= 1.1e-7 rel
#define RAD  26.0f      // attn row radius (covers all band-nonzero interior)
#define TAILG 50.0f     // tail token slack
#define BW   16         // band width (tokens per l)
#define WU   32         // union window cap in aligned
#define LT2  16         // l's per aligned block

__device__ float  g_starts[BB * TT];
__device__ int    g_tlocnt[BB * LL];         // tlo | (cnt<<16)
__device__ float4 g_band4 [BB * LL * 4];     // [bl][j/4], l-major, normalized

// ---------------------------------------------------------------------------
// Fast 2^x for x in [-126, 0]; ~2e-6 relative accuracy, FMA pipe only.
// ---------------------------------------------------------------------------
__device__ __forceinline__ float exp2_fast(float x) {
    float t = __fadd_rn(x, 12582912.0f);
    int   e = __float_as_int(t) - 0x4B400000;
    float f = __fsub_rn(x, __fsub_rn(t, 12582912.0f));
    float p =             1.3333558e-3f;
    p = fmaf(p, f, 9.6181291e-3f);
    p = fmaf(p, f, 5.5504109e-2f);
    p = fmaf(p, f, 2.4022651e-1f);
    p = fmaf(p, f, 6.9314718e-1f);
    p = fmaf(p, f, 1.0f);
    return p * __int_as_float((e + 127) << 23);
}

__device__ __forceinline__ float gw(float lf, float st, float dmin2) {
    float d = lf - st;
    float arg = fmaxf((dmin2 - d * d) * C2, -125.0f);
    return exp2_fast(arg);
}

// ---------------------------------------------------------------------------
// K1: prep (R11 fused form).  512 threads: fp64 scan (1 token/thread),
// then 2 threads per l (searches duplicated, 8 exps per thread,
// shfl-combined sum).  Band stored l-major as float4s.
// ---------------------------------------------------------------------------
__global__ void __launch_bounds__(512)
prep_kernel(const float* __restrict__ dur) {
    __shared__ float  s[TT];
    __shared__ double wsum[16];
    int b   = blockIdx.y;
    int tid = threadIdx.x;
    int lane = tid & 31, warp = tid >> 5;

    float v = dur[b * TT + tid];
    double d = (double)v;
    #pragma unroll
    for (int off = 1; off < 32; off <<= 1) {
        double n = __shfl_up_sync(0xffffffffu, d, off);
        if (lane >= off) d += n;
    }
    if (lane == 31) wsum[warp] = d;
    __syncthreads();
    if (tid < 16) {
        double w = wsum[tid];
        #pragma unroll
        for (int off = 1; off < 16; off <<= 1) {
            double n = __shfl_up_sync(0xffffu, w, off);
            if (tid >= off) w += n;
        }
        wsum[tid] = w;
    }
    __syncthreads();
    double base = warp ? wsum[warp - 1] : 0.0;
    float sv = (float)(base + d - (double)v);   // exclusive start
    s[tid] = sv;
    if (blockIdx.x == 0)
        g_starts[b * TT + tid] = sv;
    __syncthreads();

    // two threads per l
    int l    = blockIdx.x * 256 + (tid >> 1);
    int half = tid & 1;
    float lf = (float)l;

    // nearest token: last t with s[t] <= lf
    int last = 0;
    #pragma unroll
    for (int step = 256; step > 0; step >>= 1) {
        int c = last + step;
        if (c < TT && s[c] <= lf) last = c;
    }
    int tn = last;
    float d0 = lf - s[last];
    float dmin2 = d0 * d0;
    if (last + 1 < TT) {
        float d1 = s[last + 1] - lf;
        if (d1 * d1 < dmin2) { tn = last + 1; dmin2 = d1 * d1; }
    }
    float limit = dmin2 + WLIM;
    float r  = sqrtf(limit);
    float lb = lf - r;
    float ub = lf + r;

    // two independent 9-step searches
    int p1 = 0, p2 = 0;
    #pragma unroll
    for (int step = 256; step > 0; step >>= 1) {
        int c1 = p1 + step, c2 = p2 + step;
        if (c1 < TT && s[c1] <  lb) p1 = c1;
        if (c2 < TT && s[c2] <= ub) p2 = c2;
    }
    int lo = (s[0] < lb) ? p1 + 1 : 0;
    int hi = p2;
    lo = max(lo, tn - 12);  lo = min(lo, tn);
    hi = min(hi, tn + 12);  hi = max(hi, tn);
    if (hi - lo + 1 > BW) {
        #pragma unroll
        for (int i = 0; i < 9; i++) {
            if (hi - lo + 1 > BW) {
                float dl = lf - s[lo], dh = s[hi] - lf;
                if (dl >= dh) lo++; else hi--;
            }
        }
    }
    int cnt = min(hi - lo + 1, BW);

    // 8 exps per thread (j = half*8 + jj), pair-combined sum
    float ws[8];
    float sum = 0.0f;
    #pragma unroll
    for (int jj = 0; jj < 8; jj++) {
        int j = half * 8 + jj;
        int t = min(lo + j, TT - 1);
        float w = (j < cnt) ? gw(lf, s[t], dmin2) : 0.0f;
        ws[jj] = w;
        sum += w;
    }
    sum += __shfl_xor_sync(0xffffffffu, sum, 1);
    float inv = 1.0f / sum;
    int bl = b * LL + l;
    float4* bp = g_band4 + (size_t)bl * 4 + half * 2;
    bp[0] = make_float4(ws[0] * inv, ws[1] * inv, ws[2] * inv, ws[3] * inv);
    bp[1] = make_float4(ws[4] * inv, ws[5] * inv, ws[6] * inv, ws[7] * inv);
    if (half == 0)
        g_tlocnt[bl] = lo | (cnt << 16);
}

// ---------------------------------------------------------------------------
// K2: attn rows from band (run BEFORE aligned: DRAM-bound, clock-ramp
// insensitive).  One warp per (b,t) row; streaming stores.
// ---------------------------------------------------------------------------
__global__ void attn_rows_kernel(float* __restrict__ attn) {
    int warp = threadIdx.x >> 5, lane = threadIdx.x & 31;
    int row  = blockIdx.x * 8 + warp;
    int b = row / TT, t = row % TT;

    float st    = g_starts[b * TT + t];
    float slast = g_starts[b * TT + TT - 1];
    bool  tail  = (st >= slast - TAILG);
    int lmin = max(0, (int)floorf(st - RAD));
    int lmax = tail ? (LL - 1) : min(LL - 1, (int)ceilf(st + RAD));

    const int*   tlc = g_tlocnt + b * LL;
    const float* bnd = (const float*)g_band4;
    float4* rowp = (float4*)(attn + ((size_t)b * TT + t) * LL);

    #pragma unroll
    for (int k = 0; k < 16; k++) {
        int l0 = 128 * k + 4 * lane;
        float4 vq = make_float4(0.f, 0.f, 0.f, 0.f);
        if (l0 + 3 >= lmin && l0 <= lmax) {
            float* vp = &vq.x;
            #pragma unroll
            for (int j = 0; j < 4; j++) {
                int l = l0 + j;
                if (l >= lmin && l <= lmax) {
                    int off = t - (tlc[l] & 0xffff);
                    if (off >= 0 && off < BW)
                        vp[j] = bnd[(size_t)(b * LL + l) * BW + off];
                }
            }
        }
        __stcs(rowp + (l0 >> 2), vq);
    }
}

// ---------------------------------------------------------------------------
// K3: aligned (proven R10/R11 shape: 4-l groups x half-D warps, unroll 2,
// coalesced float4 band fill + smem scatter).  Runs last, at full clocks.
// ---------------------------------------------------------------------------
__device__ __forceinline__ void fma4(float4& a, float w, float4 v) {
    a.x = fmaf(w, v.x, a.x); a.y = fmaf(w, v.y, a.y);
    a.z = fmaf(w, v.z, a.z); a.w = fmaf(w, v.w, a.w);
}

__global__ void __launch_bounds__(256, 4)
aligned_kernel(const float* __restrict__ x, float* __restrict__ out) {
    __shared__ float wb[LT2][WU];
    __shared__ int   tlo_s[LT2], thi_s[LT2];
    __shared__ int   ulo_s[4], ucnt_s[4];

    int b   = blockIdx.y;
    int l0  = blockIdx.x * LT2;
    int tid = threadIdx.x;

    // zero wb (512 floats)
    ((float*)wb)[tid] = 0.0f;
    ((float*)wb)[tid + 256] = 0.0f;

    if (tid < LT2) {
        int tc = g_tlocnt[b * LL + l0 + tid];
        int lo = tc & 0xffff;
        tlo_s[tid] = lo;
        thi_s[tid] = lo + (tc >> 16);        // exclusive hi
    }
    __syncthreads();
    if (tid < 4) {
        int ulo = tlo_s[4 * tid], uhi = thi_s[4 * tid];
        #pragma unroll
        for (int i = 1; i < 4; i++) {
            ulo = min(ulo, tlo_s[4 * tid + i]);
            uhi = max(uhi, thi_s[4 * tid + i]);
        }
        ulo_s[tid]  = ulo;
        ucnt_s[tid] = min(uhi - ulo, WU);
    }
    __syncthreads();
    // coalesced band fetch: 64 threads load 64 float4s (16 l x 4)
    if (tid < LT2 * 4) {
        int li = tid >> 2, q = tid & 3;
        float4 bv = g_band4[(size_t)(b * LL + l0 + li) * 4 + q];
        int sh = tlo_s[li] - ulo_s[li >> 2];    // >= 0
        int k0 = sh + 4 * q;
        if (k0 + 0 < WU) wb[li][k0 + 0] = bv.x;
        if (k0 + 1 < WU) wb[li][k0 + 1] = bv.y;
        if (k0 + 2 < WU) wb[li][k0 + 2] = bv.z;
        if (k0 + 3 < WU) wb[li][k0 + 3] = bv.w;
    }
    __syncthreads();

    int warp = tid >> 5, lane = tid & 31;
    int g = warp >> 1;          // l-group (0..3)
    int h = warp & 1;           // D half
    int ulo  = ulo_s[g];
    int ucnt = ucnt_s[g];
    int wrow = g * 4;

    float4 a00 = make_float4(0.f,0.f,0.f,0.f), a01 = a00;
    float4 a10 = a00, a11 = a00;
    float4 a20 = a00, a21 = a00;
    float4 a30 = a00, a31 = a00;

    const float4* xb =
        (const float4*)(x + ((size_t)b * TT + ulo) * DD) + h * 64 + lane;
    #pragma unroll 2
    for (int k = 0; k < ucnt; k++) {
        const float4* xr = xb + (size_t)k * (DD / 4);
        float4 v0 = xr[0], v1 = xr[32];
        float w0 = wb[wrow + 0][k];
        float w1 = wb[wrow + 1][k];
        float w2 = wb[wrow + 2][k];
        float w3 = wb[wrow + 3][k];
        fma4(a00, w0, v0); fma4(a01, w0, v1);
        fma4(a10, w1, v0); fma4(a11, w1, v1);
        fma4(a20, w2, v0); fma4(a21, w2, v1);
        fma4(a30, w3, v0); fma4(a31, w3, v1);
    }

    {
        float4* op = (float4*)(out + ((size_t)b * LL + (l0 + wrow + 0)) * DD)
                     + h * 64 + lane;
        __stcs(op, a00); __stcs(op + 32, a01);
    }
    {
        float4* op = (float4*)(out + ((size_t)b * LL + (l0 + wrow + 1)) * DD)
                     + h * 64 + lane;
        __stcs(op, a10); __stcs(op + 32, a11);
    }
    {
        float4* op = (float4*)(out + ((size_t)b * LL + (l0 + wrow + 2)) * DD)
                     + h * 64 + lane;
        __stcs(op, a20); __stcs(op + 32, a21);
    }
    {
        float4* op = (float4*)(out + ((size_t)b * LL + (l0 + wrow + 3)) * DD)
                     + h * 64 + lane;
        __stcs(op, a30); __stcs(op + 32, a31);
    }
}

// ---------------------------------------------------------------------------
extern "C" void kernel_launch(void* const* d_in, const int* in_sizes, int n_in,
                              void* d_out, int out_size) {
    const float* x   = (const float*)d_in[0];
    const float* dur = (const float*)d_in[1];
    float* out     = (float*)d_out;
    float* aligned = out;                          // (B, L, D)
    float* attn    = out + (size_t)BB * LL * DD;   // (B, T, L)

    prep_kernel<<<dim3(LL / 256, BB), 512>>>(dur);
    attn_rows_kernel<<<(BB * TT) / 8, 256>>>(attn);
    aligned_kernel<<<dim3(LL / LT2, BB), 256>>>(x, aligned);
}